// round 12
// baseline (speedup 1.0000x reference)
#include <cuda_runtime.h>
#include <cuda_fp16.h>
#include <cstdint>

// GroupFC: h[B,G,D], W[G,D,K], out[B,G,K]; out = normalize(h) @ normalize_d(W)
#define B_SZ 256
#define G_SZ 100
#define D_SZ 768
#define K_SZ 128

#define BM 64
#define BN 128
#define BK 64
#define NT (D_SZ / BK)           // 12
#define SAU 36                   // uints per A row: 32 fp16x2 + 4 pad (144 B)
#define SBU 136                  // uints per B d2-row: 128 + 8 pad
#define SA_ST (BM * SAU)         // 2304 uints / stage
#define SA_BYTES (SA_ST * 4)     // 9216
#define SB_ST ((BK / 2) * SBU)   // 4352 uints / stage
#define SB_BYTES (SB_ST * 4)     // 17408

// dynamic smem layout (uint32 indices)
#define OFF_B   (2 * SA_ST)                  // 4608
#define OFF_HS  (OFF_B + 2 * SB_ST)          // 13312
#define OFF_WP  (OFF_HS + BM)                // 13376
#define OFF_WS  (OFF_WP + 8 * BN)            // 14400
#define SMEM_BYTES ((OFF_WS + BN) * 4)       // 58112

// pack two floats to fp16x2 (lo = first element). cvt.f16x2 packs src1->hi.
__device__ __forceinline__ uint32_t packh2(float lo, float hi) {
    uint32_t u;
    asm("cvt.rn.f16x2.f32 %0, %1, %2;" : "=r"(u) : "f"(hi), "f"(lo));
    return u;
}

__global__ __launch_bounds__(256, 3)
void groupfc_h2(const float* __restrict__ h,
                const float* __restrict__ w,
                float* __restrict__ out) {
    extern __shared__ uint32_t smem[];
    uint32_t* uA   = smem;
    uint32_t* uB   = smem + OFF_B;
    float* hsum    = reinterpret_cast<float*>(smem + OFF_HS);
    float* wpart   = reinterpret_cast<float*>(smem + OFF_WP);
    float* wsum    = reinterpret_cast<float*>(smem + OFF_WS);
    const uint32_t uA_s = (uint32_t)__cvta_generic_to_shared(uA);

    const int g    = blockIdx.y;
    const int m0   = blockIdx.x * BM;
    const int tid  = threadIdx.x;
    const int lane = tid & 31;
    const int warp = tid >> 5;
    const int gid  = lane >> 2;            // 0..7
    const int tig  = lane & 3;             // 0..3
    const int wm   = warp >> 2;            // 0..1 : rows wm*32..+32
    const int wn   = warp & 3;             // 0..3 : cols wn*32..+32

    const float* hbase = h + ((size_t)m0 * G_SZ + (size_t)g) * D_SZ;
    const float* wgrp  = w + (size_t)g * D_SZ * K_SZ;
    const size_t hstride = (size_t)G_SZ * D_SZ;

    const int arow = tid >> 3;             // A rows {arow, arow+32}
    const int ac4  = tid & 7;              // A k-chunk of 4 within a half
    const int dp   = tid >> 4;             // B d-pair 0..15 within a half
    const int n8   = (tid & 15) * 8;       // B col chunk of 8

    // per-lane ldmatrix row/col offsets (x4: lanes 0-7 mat0, 8-15 mat1, ...)
    const int a_lrow = wm * 32 + (lane & 7) + ((lane >> 3) & 1) * 8;
    const int a_koff = ((lane >> 4) & 1) * 16;     // +16B for k+8 matrices

    float acc[2][4][4];
#pragma unroll
    for (int mf = 0; mf < 2; mf++)
#pragma unroll
        for (int nf = 0; nf < 4; nf++)
#pragma unroll
            for (int q = 0; q < 4; q++) acc[mf][nf][q] = 0.f;

    float asq[2] = {0.f, 0.f};
    float wsq[8] = {0, 0, 0, 0, 0, 0, 0, 0};
    float4 rA[2], rB0[2], rB1[2];

    auto ldgH = [&](int t, int hf) {
#pragma unroll
        for (int j = 0; j < 2; j++)
            rA[j] = *reinterpret_cast<const float4*>(
                hbase + (size_t)(arow + 32 * j) * hstride + t * BK + hf * 32 + ac4 * 4);
        const float* wb = wgrp + (size_t)(t * BK + hf * 32 + 2 * dp) * K_SZ + n8;
        rB0[0] = *reinterpret_cast<const float4*>(wb);
        rB0[1] = *reinterpret_cast<const float4*>(wb + 4);
        rB1[0] = *reinterpret_cast<const float4*>(wb + K_SZ);
        rB1[1] = *reinterpret_cast<const float4*>(wb + K_SZ + 4);
    };
    auto stsH = [&](int s, int hf) {
        // A: fuse h sum-of-squares (exact fp32), convert, st.v2
        uint32_t* da = uA + s * SA_ST;
#pragma unroll
        for (int j = 0; j < 2; j++) {
            float4 v = rA[j];
            asq[j] = fmaf(v.x, v.x, fmaf(v.y, v.y,
                     fmaf(v.z, v.z, fmaf(v.w, v.w, asq[j]))));
            uint2 u = make_uint2(packh2(v.x, v.y), packh2(v.z, v.w));
            *reinterpret_cast<uint2*>(da + (arow + 32 * j) * SAU + hf * 16 + ac4 * 2) = u;
        }
        // B: pack (d, d+1) per col, fuse w sum-of-squares, st.v4
        uint32_t* db = uB + s * SB_ST + (hf * 16 + dp) * SBU + n8;
#pragma unroll
        for (int q = 0; q < 2; q++) {
            float4 lo = rB0[q], hi = rB1[q];
            wsq[q * 4 + 0] = fmaf(lo.x, lo.x, fmaf(hi.x, hi.x, wsq[q * 4 + 0]));
            wsq[q * 4 + 1] = fmaf(lo.y, lo.y, fmaf(hi.y, hi.y, wsq[q * 4 + 1]));
            wsq[q * 4 + 2] = fmaf(lo.z, lo.z, fmaf(hi.z, hi.z, wsq[q * 4 + 2]));
            wsq[q * 4 + 3] = fmaf(lo.w, lo.w, fmaf(hi.w, hi.w, wsq[q * 4 + 3]));
            uint4 u = make_uint4(packh2(lo.x, hi.x), packh2(lo.y, hi.y),
                                 packh2(lo.z, hi.z), packh2(lo.w, hi.w));
            *reinterpret_cast<uint4*>(db + q * 4) = u;
        }
    };
    auto compute = [&](int s, int ks) {    // one k16 step
        uint32_t af[2][4], bf[4][2];
        const uint32_t abase = uA_s + s * SA_BYTES + ks * 32 + a_koff;
#pragma unroll
        for (int mf = 0; mf < 2; mf++) {
            uint32_t ad = abase + (uint32_t)(a_lrow + mf * 16) * 144u;
            asm volatile(
                "ldmatrix.sync.aligned.m8n8.x4.shared.b16 {%0,%1,%2,%3}, [%4];"
                : "=r"(af[mf][0]), "=r"(af[mf][1]), "=r"(af[mf][2]), "=r"(af[mf][3])
                : "r"(ad));
        }
        const uint32_t* cB = uB + s * SB_ST;
        const int kb = ks * 8;
#pragma unroll
        for (int nf = 0; nf < 4; nf++) {
            const int cb = wn * 32 + nf * 8 + gid;
            bf[nf][0] = cB[(kb + tig) * SBU + cb];
            bf[nf][1] = cB[(kb + tig + 4) * SBU + cb];
        }
#pragma unroll
        for (int mf = 0; mf < 2; mf++)
#pragma unroll
            for (int nf = 0; nf < 4; nf++) {
                asm volatile(
                    "mma.sync.aligned.m16n8k16.row.col.f32.f16.f16.f32 "
                    "{%0,%1,%2,%3}, {%4,%5,%6,%7}, {%8,%9}, {%0,%1,%2,%3};"
                    : "+f"(acc[mf][nf][0]), "+f"(acc[mf][nf][1]),
                      "+f"(acc[mf][nf][2]), "+f"(acc[mf][nf][3])
                    : "r"(af[mf][0]), "r"(af[mf][1]),
                      "r"(af[mf][2]), "r"(af[mf][3]),
                      "r"(bf[nf][0]), "r"(bf[nf][1]));
            }
    };

    // ---- prologue: stage tile 0 (both halves) ----
    ldgH(0, 0); stsH(0, 0);
    ldgH(0, 1); stsH(0, 1);
    __syncthreads();

    // ---- mainloop: 12 tiles, one barrier each, intra-tile pipelining ----
    for (int t = 0; t < NT; t++) {
        const int cur = t & 1;
        const int nxt = cur ^ 1;
        const bool more = (t + 1 < NT);
        if (more) ldgH(t + 1, 0);
        compute(cur, 0); compute(cur, 1);
        if (more) { stsH(nxt, 0); ldgH(t + 1, 1); }
        compute(cur, 2); compute(cur, 3);
        if (more) stsH(nxt, 1);
        __syncthreads();
    }

    // ---- norm reductions (raw sums; rsqrt inline in epilogue) ----
#pragma unroll
    for (int j = 0; j < 2; j++) {          // 8 lanes share each h row
        float s = asq[j];
        s += __shfl_xor_sync(0xffffffffu, s, 1);
        s += __shfl_xor_sync(0xffffffffu, s, 2);
        s += __shfl_xor_sync(0xffffffffu, s, 4);
        if ((lane & 7) == 0) hsum[arow + 32 * j] = s;
    }
    {
        // threads sharing a column: same (tid&15) -> lane, lane+16
#pragma unroll
        for (int c = 0; c < 8; c++)
            wsq[c] += __shfl_xor_sync(0xffffffffu, wsq[c], 16);
        if (lane < 16) {
#pragma unroll
            for (int c = 0; c < 8; c++)
                wpart[warp * BN + (lane & 15) * 8 + c] = wsq[c];
        }
    }
    __syncthreads();
    if (tid < BN) {
        float s = 0.f;
#pragma unroll
        for (int wp = 0; wp < 8; wp++) s += wpart[wp * BN + tid];
        wsum[tid] = s;
    }
    __syncthreads();

    // ---- epilogue: scale by 1/(||h_row||*||w_col||), store ----
#pragma unroll
    for (int mf = 0; mf < 2; mf++) {
        int r  = wm * 32 + mf * 16 + gid;
        int b0 = m0 + r;
        float rh0 = 1.0f / fmaxf(sqrtf(hsum[r]), 1e-12f);
        float rh1 = 1.0f / fmaxf(sqrtf(hsum[r + 8]), 1e-12f);
        float* o0 = out + ((size_t)b0 * G_SZ + g) * K_SZ;
        float* o1 = o0 + (size_t)8 * G_SZ * K_SZ;
#pragma unroll
        for (int nf = 0; nf < 4; nf++) {
            int c = wn * 32 + nf * 8 + tig * 2;
            float rw0 = 1.0f / fmaxf(sqrtf(wsum[c]), 1e-12f);
            float rw1 = 1.0f / fmaxf(sqrtf(wsum[c + 1]), 1e-12f);
            float2 v0 = make_float2(acc[mf][nf][0] * rh0 * rw0,
                                    acc[mf][nf][1] * rh0 * rw1);
            float2 v1 = make_float2(acc[mf][nf][2] * rh1 * rw0,
                                    acc[mf][nf][3] * rh1 * rw1);
            *reinterpret_cast<float2*>(o0 + c) = v0;
            *reinterpret_cast<float2*>(o1 + c) = v1;
        }
    }
}

extern "C" void kernel_launch(void* const* d_in, const int* in_sizes, int n_in,
                              void* d_out, int out_size) {
    const float* h = (const float*)d_in[0];   // [B,G,D]
    const float* w = (const float*)d_in[1];   // [G,D,K]
    float* out     = (float*)d_out;           // [B,G,K]
    (void)in_sizes; (void)n_in; (void)out_size;

    cudaFuncSetAttribute(groupfc_h2,
                         cudaFuncAttributeMaxDynamicSharedMemorySize, SMEM_BYTES);
    groupfc_h2<<<dim3(B_SZ / BM, G_SZ), 256, SMEM_BYTES>>>(h, w, out);
}

// round 13
// speedup vs baseline: 1.1546x; 1.1546x over previous
#include <cuda_runtime.h>
#include <cuda_fp16.h>
#include <cstdint>

// GroupFC: h[B,G,D], W[G,D,K], out[B,G,K]; out = normalize(h) @ normalize_d(W)
#define B_SZ 256
#define G_SZ 100
#define D_SZ 768
#define K_SZ 128

#define BM 64
#define BN 128
#define BK 32
#define NT (D_SZ / BK)           // 24
#define SAU 20                   // uints per A row: 16 fp16x2 + 4 pad
#define SBU 136                  // uints per B d2-row: 128 + 8 pad
#define SA_ST (BM * SAU)         // 1280 uints / stage
#define SB_ST ((BK / 2) * SBU)   // 2176 uints / stage

// pack two floats to fp16x2 (lo = first element). cvt.f16x2 packs src1->hi.
__device__ __forceinline__ uint32_t packh2(float lo, float hi) {
    uint32_t u;
    asm("cvt.rn.f16x2.f32 %0, %1, %2;" : "=r"(u) : "f"(hi), "f"(lo));
    return u;
}

__global__ __launch_bounds__(256, 3)
void groupfc_h2(const float* __restrict__ h,
                const float* __restrict__ w,
                float* __restrict__ out) {
    // static smem: 3*(1280+2176)*4 + 256 + 4096 + 512 = 46336 B (< 48K static)
    __shared__ uint32_t uA[3 * SA_ST];     // A tiles, fp16x2 pairs along k
    __shared__ uint32_t uB[3 * SB_ST];     // B tiles, fp16x2 (d,d+1), d2-major
    __shared__ float hsum[BM];             // raw sum h^2 per local row
    __shared__ float wpart[8 * BN];        // per-warp partial sum w^2 per col
    __shared__ float wsum[BN];             // raw sum w^2 per col

    const int g    = blockIdx.y;
    const int m0   = blockIdx.x * BM;
    const int tid  = threadIdx.x;
    const int lane = tid & 31;
    const int warp = tid >> 5;
    const int gid  = lane >> 2;            // 0..7
    const int tig  = lane & 3;             // 0..3
    const int wm   = warp >> 2;            // 0..1 : rows wm*32..+32
    const int wn   = warp & 3;             // 0..3 : cols wn*32..+32

    const float* hbase = h + ((size_t)m0 * G_SZ + (size_t)g) * D_SZ;
    const float* wgrp  = w + (size_t)g * D_SZ * K_SZ;
    const size_t hstride = (size_t)G_SZ * D_SZ;

    const int arow = tid >> 3;             // A rows {arow, arow+32}
    const int ac4  = tid & 7;              // A k-chunk of 4
    const int dp   = tid >> 4;             // B d-pair 0..15 (d = 2dp, 2dp+1)
    const int n8   = (tid & 15) * 8;       // B col chunk of 8

    float acc[2][4][4];
#pragma unroll
    for (int mf = 0; mf < 2; mf++)
#pragma unroll
        for (int nf = 0; nf < 4; nf++)
#pragma unroll
            for (int q = 0; q < 4; q++) acc[mf][nf][q] = 0.f;

    float asq[2] = {0.f, 0.f};
    float wsq[8] = {0, 0, 0, 0, 0, 0, 0, 0};
    float4 rA[2], rB0[2], rB1[2];

    auto ldg = [&](int t) {
#pragma unroll
        for (int j = 0; j < 2; j++)
            rA[j] = *reinterpret_cast<const float4*>(
                hbase + (size_t)(arow + 32 * j) * hstride + t * BK + ac4 * 4);
        const float* wb = wgrp + (size_t)(t * BK + 2 * dp) * K_SZ + n8;
        rB0[0] = *reinterpret_cast<const float4*>(wb);
        rB0[1] = *reinterpret_cast<const float4*>(wb + 4);
        rB1[0] = *reinterpret_cast<const float4*>(wb + K_SZ);
        rB1[1] = *reinterpret_cast<const float4*>(wb + K_SZ + 4);
    };
    auto sts = [&](int s) {
        // A: fuse h sum-of-squares (exact fp32), convert, st.v2
        uint32_t* da = uA + s * SA_ST;
#pragma unroll
        for (int j = 0; j < 2; j++) {
            float4 v = rA[j];
            asq[j] = fmaf(v.x, v.x, fmaf(v.y, v.y,
                     fmaf(v.z, v.z, fmaf(v.w, v.w, asq[j]))));
            uint2 u = make_uint2(packh2(v.x, v.y), packh2(v.z, v.w));
            *reinterpret_cast<uint2*>(da + (arow + 32 * j) * SAU + ac4 * 2) = u;
        }
        // B: pack (d, d+1) per col, fuse w sum-of-squares, st.v4
        uint32_t* db = uB + s * SB_ST + dp * SBU + n8;
#pragma unroll
        for (int q = 0; q < 2; q++) {
            float4 lo = rB0[q], hi = rB1[q];
            wsq[q * 4 + 0] = fmaf(lo.x, lo.x, fmaf(hi.x, hi.x, wsq[q * 4 + 0]));
            wsq[q * 4 + 1] = fmaf(lo.y, lo.y, fmaf(hi.y, hi.y, wsq[q * 4 + 1]));
            wsq[q * 4 + 2] = fmaf(lo.z, lo.z, fmaf(hi.z, hi.z, wsq[q * 4 + 2]));
            wsq[q * 4 + 3] = fmaf(lo.w, lo.w, fmaf(hi.w, hi.w, wsq[q * 4 + 3]));
            uint4 u = make_uint4(packh2(lo.x, hi.x), packh2(lo.y, hi.y),
                                 packh2(lo.z, hi.z), packh2(lo.w, hi.w));
            *reinterpret_cast<uint4*>(db + q * 4) = u;
        }
    };
    auto compute = [&](int s) {
        const uint32_t* cA = uA + s * SA_ST;
        const uint32_t* cB = uB + s * SB_ST;
#pragma unroll
        for (int ks = 0; ks < 2; ks++) {           // two k16 steps per BK=32
            const int kb = ks * 8;
            uint32_t af[2][4], bf[4][2];
#pragma unroll
            for (int mf = 0; mf < 2; mf++) {
                const uint32_t* p = cA + (wm * 32 + mf * 16 + gid) * SAU + kb + tig;
                af[mf][0] = p[0];
                af[mf][1] = p[8 * SAU];
                af[mf][2] = p[4];
                af[mf][3] = p[8 * SAU + 4];
            }
#pragma unroll
            for (int nf = 0; nf < 4; nf++) {
                const int cb = wn * 32 + nf * 8 + gid;
                bf[nf][0] = cB[(kb + tig) * SBU + cb];
                bf[nf][1] = cB[(kb + tig + 4) * SBU + cb];
            }
#pragma unroll
            for (int mf = 0; mf < 2; mf++)
#pragma unroll
                for (int nf = 0; nf < 4; nf++) {
                    asm volatile(
                        "mma.sync.aligned.m16n8k16.row.col.f32.f16.f16.f32 "
                        "{%0,%1,%2,%3}, {%4,%5,%6,%7}, {%8,%9}, {%0,%1,%2,%3};"
                        : "+f"(acc[mf][nf][0]), "+f"(acc[mf][nf][1]),
                          "+f"(acc[mf][nf][2]), "+f"(acc[mf][nf][3])
                        : "r"(af[mf][0]), "r"(af[mf][1]),
                          "r"(af[mf][2]), "r"(af[mf][3]),
                          "r"(bf[nf][0]), "r"(bf[nf][1]));
                }
        }
    };

    // ---- prologue: stage tile 0; preload tile 1 into regs ----
    ldg(0); sts(0);
    ldg(1);
    __syncthreads();

    // ---- mainloop: 3-stage buffer, 2-tile LDG lookahead, 1 barrier/tile ----
    // iter t: sts(t+1) [regs->smem, loaded last iter], ldg(t+2) [fresh, ~2
    // tiles of latency cover], compute(t), barrier.
    int s_cmp = 0, s_sts = 1;
    for (int t = 0; t < NT; t++) {
        if (t + 1 < NT) sts(s_sts);
        if (t + 2 < NT) ldg(t + 2);
        compute(s_cmp);
        __syncthreads();
        s_cmp = (s_cmp == 2) ? 0 : s_cmp + 1;
        s_sts = (s_sts == 2) ? 0 : s_sts + 1;
    }

    // ---- norm reductions (raw sums; rsqrt inline in epilogue) ----
#pragma unroll
    for (int j = 0; j < 2; j++) {          // 8 lanes share each h row
        float s = asq[j];
        s += __shfl_xor_sync(0xffffffffu, s, 1);
        s += __shfl_xor_sync(0xffffffffu, s, 2);
        s += __shfl_xor_sync(0xffffffffu, s, 4);
        if ((lane & 7) == 0) hsum[arow + 32 * j] = s;
    }
    {
        // threads sharing a column: same (tid&15) -> lane, lane+16
#pragma unroll
        for (int c = 0; c < 8; c++)
            wsq[c] += __shfl_xor_sync(0xffffffffu, wsq[c], 16);
        if (lane < 16) {
#pragma unroll
            for (int c = 0; c < 8; c++)
                wpart[warp * BN + (lane & 15) * 8 + c] = wsq[c];
        }
    }
    __syncthreads();
    if (tid < BN) {
        float s = 0.f;
#pragma unroll
        for (int wp = 0; wp < 8; wp++) s += wpart[wp * BN + tid];
        wsum[tid] = s;
    }
    __syncthreads();

    // ---- epilogue: scale by 1/(||h_row||*||w_col||), store ----
#pragma unroll
    for (int mf = 0; mf < 2; mf++) {
        int r  = wm * 32 + mf * 16 + gid;
        int b0 = m0 + r;
        float rh0 = 1.0f / fmaxf(sqrtf(hsum[r]), 1e-12f);
        float rh1 = 1.0f / fmaxf(sqrtf(hsum[r + 8]), 1e-12f);
        float* o0 = out + ((size_t)b0 * G_SZ + g) * K_SZ;
        float* o1 = o0 + (size_t)8 * G_SZ * K_SZ;
#pragma unroll
        for (int nf = 0; nf < 4; nf++) {
            int c = wn * 32 + nf * 8 + tig * 2;
            float rw0 = 1.0f / fmaxf(sqrtf(wsum[c]), 1e-12f);
            float rw1 = 1.0f / fmaxf(sqrtf(wsum[c + 1]), 1e-12f);
            float2 v0 = make_float2(acc[mf][nf][0] * rh0 * rw0,
                                    acc[mf][nf][1] * rh0 * rw1);
            float2 v1 = make_float2(acc[mf][nf][2] * rh1 * rw0,
                                    acc[mf][nf][3] * rh1 * rw1);
            *reinterpret_cast<float2*>(o0 + c) = v0;
            *reinterpret_cast<float2*>(o1 + c) = v1;
        }
    }
}

extern "C" void kernel_launch(void* const* d_in, const int* in_sizes, int n_in,
                              void* d_out, int out_size) {
    const float* h = (const float*)d_in[0];   // [B,G,D]
    const float* w = (const float*)d_in[1];   // [G,D,K]
    float* out     = (float*)d_out;           // [B,G,K]
    (void)in_sizes; (void)n_in; (void)out_size;

    groupfc_h2<<<dim3(B_SZ / BM, G_SZ), 256>>>(h, w, out);
}

// round 15
// speedup vs baseline: 1.3555x; 1.1740x over previous
#include <cuda_runtime.h>
#include <cuda_fp16.h>
#include <cstdint>

// GroupFC: h[B,G,D], W[G,D,K], out[B,G,K]; out = normalize(h) @ normalize_d(W)
#define B_SZ 256
#define G_SZ 100
#define D_SZ 768
#define K_SZ 128

#define BM 64
#define BN 128
#define BK 32
#define NT (D_SZ / BK)           // 24
#define SAU 20                   // uints per A row: 16 fp16x2 + 4 pad
#define SA_ST (BM * SAU)         // 1280 uints / stage (A: fp16, 2 stages)
#define SBF 132                  // floats per B row: 128 + 4 pad
#define SB_ST (BK * SBF)         // 4224 floats / stage (B: fp32, 3 stages)
#define SB_BYTES (SB_ST * 4)     // 16896 B / stage

// dynamic smem (uint32 words): A 2*1280 | B 3*4224 | hsum 64 | wsum 128
#define OFF_B   (2 * SA_ST)
#define OFF_HS  (OFF_B + 3 * SB_ST)
#define OFF_WS  (OFF_HS + BM)
#define SMEM_BYTES ((OFF_WS + BN) * 4)   // 61,696 B

// pack two floats to fp16x2 (lo = first element).
__device__ __forceinline__ uint32_t packh2(float lo, float hi) {
    uint32_t u;
    asm("cvt.rn.f16x2.f32 %0, %1, %2;" : "=r"(u) : "f"(hi), "f"(lo));
    return u;
}
__device__ __forceinline__ void cp16(uint32_t saddr, const float* gaddr) {
    asm volatile("cp.async.cg.shared.global [%0], [%1], 16;"
                 :: "r"(saddr), "l"(gaddr));
}

__global__ __launch_bounds__(256, 3)
void groupfc_h2(const float* __restrict__ h,
                const float* __restrict__ w,
                float* __restrict__ out) {
    extern __shared__ uint32_t smem[];
    uint32_t* uA = smem;                                   // fp16x2 A tiles
    float* fB    = reinterpret_cast<float*>(smem + OFF_B); // fp32 B ring (3)
    float* hsum  = reinterpret_cast<float*>(smem + OFF_HS);
    float* wsum  = reinterpret_cast<float*>(smem + OFF_WS);
    const uint32_t fB_s = (uint32_t)__cvta_generic_to_shared(fB);

    const int g    = blockIdx.y;
    const int m0   = blockIdx.x * BM;
    const int tid  = threadIdx.x;
    const int lane = tid & 31;
    const int warp = tid >> 5;
    const int gid  = lane >> 2;            // 0..7
    const int tig  = lane & 3;             // 0..3
    const int wm   = warp >> 2;            // 0..1 : rows wm*32..+32
    const int wn   = warp & 3;             // 0..3 : cols wn*32..+32

    const float* hbase = h + ((size_t)m0 * G_SZ + (size_t)g) * D_SZ;
    const float* wgrp  = w + (size_t)g * D_SZ * K_SZ;
    const size_t hstride = (size_t)G_SZ * D_SZ;

    const int arow = tid >> 3;             // A rows {arow, arow+32}
    const int ac4  = tid & 7;              // A k-chunk of 4

    float acc[2][4][4];
#pragma unroll
    for (int mf = 0; mf < 2; mf++)
#pragma unroll
        for (int nf = 0; nf < 4; nf++)
#pragma unroll
            for (int q = 0; q < 4; q++) acc[mf][nf][q] = 0.f;

    float asq[2] = {0.f, 0.f};
    float wsq[4] = {0.f, 0.f, 0.f, 0.f};
    float4 rA[2];

    auto cpB = [&](int t) {                // gmem -> smem ring, RF-bypassing
        const int s = t % 3;
#pragma unroll
        for (int j = 0; j < 4; j++) {
            int id  = tid + j * 256;       // 0..1023 chunks of 16B
            int row = id >> 5;             // 0..31 (d within tile)
            int c16 = id & 31;             // 16B column chunk
            cp16(fB_s + (uint32_t)(s * SB_BYTES + row * (SBF * 4) + c16 * 16),
                 wgrp + (size_t)(t * BK + row) * K_SZ + c16 * 4);
        }
        asm volatile("cp.async.commit_group;");
    };
    auto ldgA = [&](int t) {
#pragma unroll
        for (int j = 0; j < 2; j++)
            rA[j] = *reinterpret_cast<const float4*>(
                hbase + (size_t)(arow + 32 * j) * hstride + t * BK + ac4 * 4);
    };
    auto stsA = [&](int s) {               // s = STAGE (0/1); fused h sumsq
        uint32_t* da = uA + s * SA_ST;
#pragma unroll
        for (int j = 0; j < 2; j++) {
            float4 v = rA[j];
            asq[j] = fmaf(v.x, v.x, fmaf(v.y, v.y,
                     fmaf(v.z, v.z, fmaf(v.w, v.w, asq[j]))));
            uint2 u = make_uint2(packh2(v.x, v.y), packh2(v.z, v.w));
            *reinterpret_cast<uint2*>(da + (arow + 32 * j) * SAU + ac4 * 2) = u;
        }
    };
    auto compute = [&](int t) {
        const uint32_t* cA = uA + (t & 1) * SA_ST;
        const float* cB = fB + (t % 3) * SB_ST;
#pragma unroll
        for (int ks = 0; ks < 2; ks++) {           // two k16 steps
            uint32_t af[2][4], bf[4][2];
#pragma unroll
            for (int mf = 0; mf < 2; mf++) {
                const uint32_t* p = cA + (wm * 32 + mf * 16 + gid) * SAU
                                       + ks * 8 + tig;
                af[mf][0] = p[0];
                af[mf][1] = p[8 * SAU];
                af[mf][2] = p[4];
                af[mf][3] = p[8 * SAU + 4];
            }
            const float* br = cB + (ks * 16 + 2 * tig) * SBF
                                 + wn * 32 + gid;
#pragma unroll
            for (int nf = 0; nf < 4; nf++) {
                float b00 = br[nf * 8];
                float b01 = br[nf * 8 + SBF];
                float b10 = br[nf * 8 + 8 * SBF];
                float b11 = br[nf * 8 + 9 * SBF];
                if (wm == 0)               // each B element seen once by wm=0
                    wsq[nf] = fmaf(b00, b00, fmaf(b01, b01,
                              fmaf(b10, b10, fmaf(b11, b11, wsq[nf]))));
                bf[nf][0] = packh2(b00, b01);
                bf[nf][1] = packh2(b10, b11);
            }
#pragma unroll
            for (int mf = 0; mf < 2; mf++)
#pragma unroll
                for (int nf = 0; nf < 4; nf++) {
                    asm volatile(
                        "mma.sync.aligned.m16n8k16.row.col.f32.f16.f16.f32 "
                        "{%0,%1,%2,%3}, {%4,%5,%6,%7}, {%8,%9}, {%0,%1,%2,%3};"
                        : "+f"(acc[mf][nf][0]), "+f"(acc[mf][nf][1]),
                          "+f"(acc[mf][nf][2]), "+f"(acc[mf][nf][3])
                        : "r"(af[mf][0]), "r"(af[mf][1]),
                          "r"(af[mf][2]), "r"(af[mf][3]),
                          "r"(bf[nf][0]), "r"(bf[nf][1]));
                }
        }
    };

    // ---- prologue: B tiles 0,1 in flight; A tile 0 staged ----
    cpB(0);
    cpB(1);
    ldgA(0); stsA(0);

    // ---- mainloop: one barrier/tile; cpB lands 2 tiles ahead ----
    for (int t = 0; t < NT; t++) {
        if (t + 1 < NT) ldgA(t + 1);
        if (t == NT - 1)
            asm volatile("cp.async.wait_group 0;");   // last tile fully landed
        else
            asm volatile("cp.async.wait_group 1;");   // B(t) landed
        __syncthreads();                              // + all past compute(t-1)
        if (t + 2 < NT) cpB(t + 2);                   // slot (t+2)%3 now free
        compute(t);
        if (t + 1 < NT) stsA((t + 1) & 1);            // STAGE index (bugfix)
    }

    // ---- norm reductions ----
#pragma unroll
    for (int j = 0; j < 2; j++) {          // 8 lanes share each h row
        float s = asq[j];
        s += __shfl_xor_sync(0xffffffffu, s, 1);
        s += __shfl_xor_sync(0xffffffffu, s, 2);
        s += __shfl_xor_sync(0xffffffffu, s, 4);
        if ((lane & 7) == 0) hsum[arow + 32 * j] = s;
    }
    if (wm == 0) {                         // 4 tig lanes share each w column
#pragma unroll
        for (int nf = 0; nf < 4; nf++) {
            float s = wsq[nf];
            s += __shfl_xor_sync(0xffffffffu, s, 1);
            s += __shfl_xor_sync(0xffffffffu, s, 2);
            if (tig == 0) wsum[wn * 32 + nf * 8 + gid] = s;
        }
    }
    __syncthreads();

    // ---- epilogue: scale by 1/(||h_row||*||w_col||), store ----
#pragma unroll
    for (int mf = 0; mf < 2; mf++) {
        int r  = wm * 32 + mf * 16 + gid;
        int b0 = m0 + r;
        float rh0 = 1.0f / fmaxf(sqrtf(hsum[r]), 1e-12f);
        float rh1 = 1.0f / fmaxf(sqrtf(hsum[r + 8]), 1e-12f);
        float* o0 = out + ((size_t)b0 * G_SZ + g) * K_SZ;
        float* o1 = o0 + (size_t)8 * G_SZ * K_SZ;
#pragma unroll
        for (int nf = 0; nf < 4; nf++) {
            int c = wn * 32 + nf * 8 + tig * 2;
            float rw0 = 1.0f / fmaxf(sqrtf(wsum[c]), 1e-12f);
            float rw1 = 1.0f / fmaxf(sqrtf(wsum[c + 1]), 1e-12f);
            float2 v0 = make_float2(acc[mf][nf][0] * rh0 * rw0,
                                    acc[mf][nf][1] * rh0 * rw1);
            float2 v1 = make_float2(acc[mf][nf][2] * rh1 * rw0,
                                    acc[mf][nf][3] * rh1 * rw1);
            *reinterpret_cast<float2*>(o0 + c) = v0;
            *reinterpret_cast<float2*>(o1 + c) = v1;
        }
    }
}

extern "C" void kernel_launch(void* const* d_in, const int* in_sizes, int n_in,
                              void* d_out, int out_size) {
    const float* h = (const float*)d_in[0];   // [B,G,D]
    const float* w = (const float*)d_in[1];   // [G,D,K]
    float* out     = (float*)d_out;           // [B,G,K]
    (void)in_sizes; (void)n_in; (void)out_size;

    cudaFuncSetAttribute(groupfc_h2,
                         cudaFuncAttributeMaxDynamicSharedMemorySize, SMEM_BYTES);
    groupfc_h2<<<dim3(B_SZ / BM, G_SZ), 256, SMEM_BYTES>>>(h, w, out);
}

// round 16
// speedup vs baseline: 1.4725x; 1.0863x over previous
#include <cuda_runtime.h>
#include <cuda_fp16.h>
#include <cstdint>

// GroupFC: h[B,G,D], W[G,D,K], out[B,G,K]; out = normalize(h) @ normalize_d(W)
#define B_SZ 256
#define G_SZ 100
#define D_SZ 768
#define K_SZ 128

#define BM 128
#define BN 64
#define BK 32
#define NT (D_SZ / BK)           // 24
#define SAU 20                   // uints per A row: 16 fp16x2 + 4 pad (80 B)
#define SA_ST (BM * SAU)         // 2560 uints / stage (A fp16, 2 stages)
#define SA_BYTES (SA_ST * 4)     // 10240
#define SBF 68                   // floats per B row: 64 + 4 pad
#define SB_ST (BK * SBF)         // 2176 floats / stage (B fp32, 3 stages)
#define SB_BYTES (SB_ST * 4)     // 8704

// pack two floats to fp16x2 (lo = first element).
__device__ __forceinline__ uint32_t packh2(float lo, float hi) {
    uint32_t u;
    asm("cvt.rn.f16x2.f32 %0, %1, %2;" : "=r"(u) : "f"(hi), "f"(lo));
    return u;
}
__device__ __forceinline__ void cp16(uint32_t saddr, const float* gaddr) {
    asm volatile("cp.async.cg.shared.global [%0], [%1], 16;"
                 :: "r"(saddr), "l"(gaddr));
}

__global__ __launch_bounds__(256, 3)
void groupfc_h2(const float* __restrict__ h,
                const float* __restrict__ w,
                float* __restrict__ out) {
    // static smem: A 20480 + B 26112 + hsum 512 + wsum 256 = 47360 B (<48K)
    __shared__ uint32_t uA[2 * SA_ST];
    __shared__ float fB[3 * SB_ST];
    __shared__ float hsum[BM];
    __shared__ float wsum[BN];
    const uint32_t uA_s = (uint32_t)__cvta_generic_to_shared(uA);
    const uint32_t fB_s = (uint32_t)__cvta_generic_to_shared(fB);

    const int g    = blockIdx.z;
    const int m0   = blockIdx.x * BM;
    const int n0   = blockIdx.y * BN;
    const int tid  = threadIdx.x;
    const int lane = tid & 31;
    const int warp = tid >> 5;
    const int gid  = lane >> 2;            // 0..7
    const int tig  = lane & 3;             // 0..3
    const int wm   = warp >> 2;            // 0..1 : rows wm*64..+64
    const int wn   = warp & 3;             // 0..3 : cols wn*16..+16

    const float* hbase = h + ((size_t)m0 * G_SZ + (size_t)g) * D_SZ;
    const float* wgrp  = w + (size_t)g * D_SZ * K_SZ + n0;
    const size_t hstride = (size_t)G_SZ * D_SZ;

    const int arow = tid >> 3;             // A rows {arow+32j}, j=0..3
    const int ac4  = tid & 7;              // A k-chunk of 4

    // per-lane ldmatrix byte offset within a fragment block
    const uint32_t a_lane = (uint32_t)((lane & 7) + ((lane >> 3) & 1) * 8) * 80u
                          + (uint32_t)((lane >> 4) & 1) * 16u;

    float acc[4][2][4];
#pragma unroll
    for (int mf = 0; mf < 4; mf++)
#pragma unroll
        for (int nf = 0; nf < 2; nf++)
#pragma unroll
            for (int q = 0; q < 4; q++) acc[mf][nf][q] = 0.f;

    float asq[4] = {0.f, 0.f, 0.f, 0.f};
    float wsq[2] = {0.f, 0.f};
    float4 rA[4];

    auto cpB = [&](int t) {                // gmem -> smem ring (RF-bypassing)
        const int s = t % 3;
#pragma unroll
        for (int j = 0; j < 2; j++) {
            int id  = tid + j * 256;       // 0..511 chunks of 16B
            int row = id >> 4;             // 0..31 (d in tile)
            int c4  = id & 15;             // 16B column chunk
            cp16(fB_s + (uint32_t)(s * SB_BYTES + row * (SBF * 4) + c4 * 16),
                 wgrp + (size_t)(t * BK + row) * K_SZ + c4 * 4);
        }
        asm volatile("cp.async.commit_group;");
    };
    auto ldgA = [&](int t) {
#pragma unroll
        for (int j = 0; j < 4; j++)
            rA[j] = *reinterpret_cast<const float4*>(
                hbase + (size_t)(arow + 32 * j) * hstride + t * BK + ac4 * 4);
    };
    auto stsA = [&](int s) {               // s = STAGE (0/1); fused h sumsq
        uint32_t* da = uA + s * SA_ST;
#pragma unroll
        for (int j = 0; j < 4; j++) {
            float4 v = rA[j];
            asq[j] = fmaf(v.x, v.x, fmaf(v.y, v.y,
                     fmaf(v.z, v.z, fmaf(v.w, v.w, asq[j]))));
            uint2 u = make_uint2(packh2(v.x, v.y), packh2(v.z, v.w));
            *reinterpret_cast<uint2*>(da + (arow + 32 * j) * SAU + ac4 * 2) = u;
        }
    };
    auto compute = [&](int t) {
        const uint32_t abase = uA_s + (t & 1) * SA_BYTES
                             + (uint32_t)(wm * 64) * 80u + a_lane;
        const float* cB = fB + (t % 3) * SB_ST;
#pragma unroll
        for (int ks = 0; ks < 2; ks++) {           // two k16 steps
            // B fragments: 8 LDS + 4 packs, amortized over 4 mf
            const float* br = cB + (ks * 16 + 2 * tig) * SBF + wn * 16 + gid;
            uint32_t bf[2][2];
#pragma unroll
            for (int nf = 0; nf < 2; nf++) {
                float b00 = br[nf * 8];
                float b01 = br[nf * 8 + SBF];
                float b10 = br[nf * 8 + 8 * SBF];
                float b11 = br[nf * 8 + 9 * SBF];
                if (wm == 0)               // each B element seen once by wm=0
                    wsq[nf] = fmaf(b00, b00, fmaf(b01, b01,
                              fmaf(b10, b10, fmaf(b11, b11, wsq[nf]))));
                bf[nf][0] = packh2(b00, b01);
                bf[nf][1] = packh2(b10, b11);
            }
#pragma unroll
            for (int mf = 0; mf < 4; mf++) {
                uint32_t af0, af1, af2, af3;
                asm volatile(
                    "ldmatrix.sync.aligned.m8n8.x4.shared.b16 {%0,%1,%2,%3}, [%4];"
                    : "=r"(af0), "=r"(af1), "=r"(af2), "=r"(af3)
                    : "r"(abase + (uint32_t)(mf * 16) * 80u + ks * 32u));
#pragma unroll
                for (int nf = 0; nf < 2; nf++) {
                    asm volatile(
                        "mma.sync.aligned.m16n8k16.row.col.f32.f16.f16.f32 "
                        "{%0,%1,%2,%3}, {%4,%5,%6,%7}, {%8,%9}, {%0,%1,%2,%3};"
                        : "+f"(acc[mf][nf][0]), "+f"(acc[mf][nf][1]),
                          "+f"(acc[mf][nf][2]), "+f"(acc[mf][nf][3])
                        : "r"(af0), "r"(af1), "r"(af2), "r"(af3),
                          "r"(bf[nf][0]), "r"(bf[nf][1]));
                }
            }
        }
    };

    // ---- prologue: B tiles 0,1 in flight; A tile 0 staged ----
    cpB(0);
    cpB(1);
    ldgA(0); stsA(0);

    // ---- mainloop: one barrier/tile; cpB lands 2 tiles ahead ----
    for (int t = 0; t < NT; t++) {
        if (t + 1 < NT) ldgA(t + 1);
        if (t == NT - 1)
            asm volatile("cp.async.wait_group 0;");
        else
            asm volatile("cp.async.wait_group 1;");   // B(t) landed
        __syncthreads();
        if (t + 2 < NT) cpB(t + 2);                   // slot (t+2)%3 free
        compute(t);
        if (t + 1 < NT) stsA((t + 1) & 1);            // stage index
    }

    // ---- norm reductions ----
#pragma unroll
    for (int j = 0; j < 4; j++) {          // 8 lanes share each h row
        float s = asq[j];
        s += __shfl_xor_sync(0xffffffffu, s, 1);
        s += __shfl_xor_sync(0xffffffffu, s, 2);
        s += __shfl_xor_sync(0xffffffffu, s, 4);
        if ((lane & 7) == 0) hsum[arow + 32 * j] = s;
    }
    if (wm == 0) {                         // 4 tig lanes share each w column
#pragma unroll
        for (int nf = 0; nf < 2; nf++) {
            float s = wsq[nf];
            s += __shfl_xor_sync(0xffffffffu, s, 1);
            s += __shfl_xor_sync(0xffffffffu, s, 2);
            if (tig == 0) wsum[wn * 16 + nf * 8 + gid] = s;
        }
    }
    __syncthreads();

    // ---- epilogue: scale by 1/(||h_row||*||w_col||), store ----
#pragma unroll
    for (int mf = 0; mf < 4; mf++) {
        int r  = wm * 64 + mf * 16 + gid;
        int b0 = m0 + r;
        float rh0 = 1.0f / fmaxf(sqrtf(hsum[r]), 1e-12f);
        float rh1 = 1.0f / fmaxf(sqrtf(hsum[r + 8]), 1e-12f);
        float* o0 = out + ((size_t)b0 * G_SZ + g) * K_SZ + n0;
        float* o1 = o0 + (size_t)8 * G_SZ * K_SZ;
#pragma unroll
        for (int nf = 0; nf < 2; nf++) {
            int c = wn * 16 + nf * 8 + tig * 2;
            float rw0 = 1.0f / fmaxf(sqrtf(wsum[c]), 1e-12f);
            float rw1 = 1.0f / fmaxf(sqrtf(wsum[c + 1]), 1e-12f);
            float2 v0 = make_float2(acc[mf][nf][0] * rh0 * rw0,
                                    acc[mf][nf][1] * rh0 * rw1);
            float2 v1 = make_float2(acc[mf][nf][2] * rh1 * rw0,
                                    acc[mf][nf][3] * rh1 * rw1);
            *reinterpret_cast<float2*>(o0 + c) = v0;
            *reinterpret_cast<float2*>(o1 + c) = v1;
        }
    }
}

extern "C" void kernel_launch(void* const* d_in, const int* in_sizes, int n_in,
                              void* d_out, int out_size) {
    const float* h = (const float*)d_in[0];   // [B,G,D]
    const float* w = (const float*)d_in[1];   // [G,D,K]
    float* out     = (float*)d_out;           // [B,G,K]
    (void)in_sizes; (void)n_in; (void)out_size;

    groupfc_h2<<<dim3(B_SZ / BM, K_SZ / BN, G_SZ), 256>>>(h, w, out);
}